// round 1
// baseline (speedup 1.0000x reference)
#include <cuda_runtime.h>
#include <math.h>

// Problem constants
#define NN   50000
#define EE   1600000
#define INF  64
#define HIDF 128
#define LATF 32
#define HARM 8
#define NL   3
#define NG   64

// ---------------- scratch (__device__ globals; no runtime allocation) ----------------
__device__ float g_h [NN * HIDF];          // current node features
__device__ float g_hk[NN * HIDF];          // kan(h) before aggregation
__device__ int   g_deg [NN];               // degree incl. self loop
__device__ float g_dinv[NN];               // deg^-0.5
__device__ int   g_off [NN + 1];           // CSR offsets (edges only, by col)
__device__ int   g_cur [NN];               // fill cursors
__device__ int   g_rows[EE];               // CSR: source row per edge
__device__ float g_nrm [EE];               // CSR: dinv[row]*dinv[col] per edge
__device__ float g_wte [1024 * 128];       // W_embed transposed  [K=1024][128]
__device__ float g_wtm [3 * 2048 * 128];   // W_mp transposed     [l][K=2048][128]
__device__ float g_wtr [2048 * 32];        // W_read transposed   [K=2048][32]
__device__ float g_pool[NG * HIDF];        // pooled graph features

// ---------------- weight repack: W[2][OUT][IN][8] -> Wt[k][o], k = i*16 + t*8 + h ----
__device__ __forceinline__ void transpose_body(const float* __restrict__ W,
                                               float* __restrict__ Wt,
                                               int INDIM, int OUT)
{
    int idx = blockIdx.x * blockDim.x + threadIdx.x;
    int total = INDIM * 16 * OUT;
    if (idx >= total) return;
    int o = idx % OUT;
    int k = idx / OUT;
    int i = k >> 4;
    int t = (k >> 3) & 1;
    int h = k & 7;
    Wt[idx] = W[(((size_t)t * OUT + o) * INDIM + i) * 8 + h];
}

__global__ void transpose_embed(const float* __restrict__ W) { transpose_body(W, g_wte, 64, 128); }
__global__ void transpose_mp(const float* __restrict__ W, int layer)
{
    transpose_body(W + (size_t)layer * 2 * 128 * 128 * 8, g_wtm + (size_t)layer * 2048 * 128, 128, 128);
}
__global__ void transpose_read(const float* __restrict__ W) { transpose_body(W, g_wtr, 128, 32); }

// ---------------- degree / dinv ----------------
__global__ void deg_init_kernel()
{
    int i = blockIdx.x * blockDim.x + threadIdx.x;
    if (i < NN) g_deg[i] = 1;   // self loop
}
__global__ void deg_count_kernel(const int* __restrict__ ei)
{
    int e = blockIdx.x * blockDim.x + threadIdx.x;
    if (e < EE) atomicAdd(&g_deg[ei[EE + e]], 1);
}
__global__ void dinv_kernel()
{
    int i = blockIdx.x * blockDim.x + threadIdx.x;
    if (i < NN) g_dinv[i] = rsqrtf((float)g_deg[i]);
}

// ---------------- CSR build: exclusive scan of (deg-1), then fill ----------------
__global__ void scan_kernel()
{
    __shared__ int part[1024];
    int t = threadIdx.x;
    const int seg = (NN + 1023) / 1024;
    int base = t * seg;
    int s = 0;
    for (int j = 0; j < seg; ++j) {
        int i = base + j;
        if (i < NN) s += g_deg[i] - 1;
    }
    part[t] = s;
    __syncthreads();
    // Hillis-Steele inclusive scan
    for (int d = 1; d < 1024; d <<= 1) {
        int v = (t >= d) ? part[t - d] : 0;
        __syncthreads();
        part[t] += v;
        __syncthreads();
    }
    int run = part[t] - s;   // exclusive prefix for this segment
    for (int j = 0; j < seg; ++j) {
        int i = base + j;
        if (i < NN) {
            g_off[i] = run;
            g_cur[i] = run;
            run += g_deg[i] - 1;
        }
    }
    if (t == 1023) g_off[NN] = part[1023];
}

__global__ void fill_kernel(const int* __restrict__ ei)
{
    int e = blockIdx.x * blockDim.x + threadIdx.x;
    if (e >= EE) return;
    int r = ei[e];
    int c = ei[EE + e];
    int pos = atomicAdd(&g_cur[c], 1);
    g_rows[pos] = r;
    g_nrm[pos]  = g_dinv[r] * g_dinv[c];
}

// ---------------- KAN GEMM: Y[rows,128] = phi(X) @ Wt ----------------
// Tile: 128 rows x 128 cols, 256 threads, 8x8 per-thread micro-tile.
// K-chunk = 32 (= 2 input dims x 16 trig features), trig built on the fly in smem.
template <int INDIM>
__device__ __forceinline__ void kan_body(const float* __restrict__ X,
                                         const float* __restrict__ Wt,
                                         float* __restrict__ Y, int nrows)
{
    __shared__ float phiS[32 * 128];  // [k_local][row]
    __shared__ float wS  [32 * 128];  // [k_local][o]

    const int tid = threadIdx.x;
    const int tx  = tid & 15;
    const int ty  = tid >> 4;
    const int rowBase = blockIdx.x * 128;

    float acc[8][8];
#pragma unroll
    for (int i = 0; i < 8; ++i)
#pragma unroll
        for (int j = 0; j < 8; ++j) acc[i][j] = 0.f;

    const int NCH = INDIM / 2;
    for (int ch = 0; ch < NCH; ++ch) {
        __syncthreads();
        if (tid < 128) {
            // one row per thread: 2 input dims -> 32 phi values
            int r = rowBase + tid;
            float x0 = 0.f, x1 = 0.f;
            if (r < nrows) {
                float2 xv = *(const float2*)(X + (size_t)r * INDIM + ch * 2);
                x0 = xv.x; x1 = xv.y;
            }
            float xs[2] = {x0, x1};
#pragma unroll
            for (int d = 0; d < 2; ++d) {
                float s1, c1;
                sincosf(xs[d], &s1, &c1);
                float ck = c1, sk = s1;
                int kb = d * 16;
#pragma unroll
                for (int hh = 0; hh < 8; ++hh) {
                    phiS[(kb + hh) * 128 + tid]     = ck;   // cos(k x), k = hh+1
                    phiS[(kb + 8 + hh) * 128 + tid] = sk;   // sin(k x)
                    float cn = ck * c1 - sk * s1;
                    sk = sk * c1 + ck * s1;
                    ck = cn;
                }
            }
        } else {
            // other 128 threads stream the W chunk (coalesced, pre-transposed)
            int t2 = tid - 128;
            const float4* src = (const float4*)(Wt + (size_t)ch * 32 * 128);
            float4* dst = (float4*)wS;
#pragma unroll
            for (int j = 0; j < 8; ++j) dst[t2 + j * 128] = src[t2 + j * 128];
        }
        __syncthreads();

#pragma unroll 4
        for (int k = 0; k < 32; ++k) {
            float4 a0 = *(const float4*)(phiS + k * 128 + ty * 8);
            float4 a1 = *(const float4*)(phiS + k * 128 + ty * 8 + 4);
            float4 b0 = *(const float4*)(wS   + k * 128 + tx * 8);
            float4 b1 = *(const float4*)(wS   + k * 128 + tx * 8 + 4);
            float a[8] = {a0.x, a0.y, a0.z, a0.w, a1.x, a1.y, a1.z, a1.w};
            float b[8] = {b0.x, b0.y, b0.z, b0.w, b1.x, b1.y, b1.z, b1.w};
#pragma unroll
            for (int i = 0; i < 8; ++i)
#pragma unroll
                for (int j = 0; j < 8; ++j)
                    acc[i][j] = fmaf(a[i], b[j], acc[i][j]);
        }
    }

#pragma unroll
    for (int i = 0; i < 8; ++i) {
        int r = rowBase + ty * 8 + i;
        if (r < nrows) {
            float4 o0 = make_float4(acc[i][0], acc[i][1], acc[i][2], acc[i][3]);
            float4 o1 = make_float4(acc[i][4], acc[i][5], acc[i][6], acc[i][7]);
            *(float4*)(Y + (size_t)r * 128 + tx * 8)     = o0;
            *(float4*)(Y + (size_t)r * 128 + tx * 8 + 4) = o1;
        }
    }
}

__global__ void __launch_bounds__(256, 2) kan_embed_kernel(const float* __restrict__ X)
{
    kan_body<64>(X, g_wte, g_h, NN);
}
__global__ void __launch_bounds__(256, 2) kan_mp_kernel(int layer)
{
    kan_body<128>(g_h, g_wtm + (size_t)layer * 2048 * 128, g_hk, NN);
}

// ---------------- aggregation: h[c] = dinv[c]^2 * hk[c] + sum_{e: col=c} nrm_e * hk[row_e] ----
// one warp per destination node, lane = float4 slot of the 128-wide feature row
__global__ void agg_kernel()
{
    int w    = (blockIdx.x * blockDim.x + threadIdx.x) >> 5;
    int lane = threadIdx.x & 31;
    if (w >= NN) return;

    float di = g_dinv[w];
    const float4* hk4 = (const float4*)g_hk;
    float4 v = hk4[(size_t)w * 32 + lane];
    float dd = di * di;
    float4 acc = make_float4(dd * v.x, dd * v.y, dd * v.z, dd * v.w);

    int s = g_off[w], e = g_off[w + 1];
    for (int idx = s; idx < e; ++idx) {
        int   r  = g_rows[idx];
        float nm = g_nrm[idx];
        float4 u = hk4[(size_t)r * 32 + lane];
        acc.x = fmaf(nm, u.x, acc.x);
        acc.y = fmaf(nm, u.y, acc.y);
        acc.z = fmaf(nm, u.z, acc.z);
        acc.w = fmaf(nm, u.w, acc.w);
    }
    ((float4*)g_h)[(size_t)w * 32 + lane] = acc;
}

// ---------------- mean pool per graph (batch ids are sorted) ----------------
__global__ void pool_kernel(const int* __restrict__ batch)
{
    int g = blockIdx.x;     // 64 graphs
    int f = threadIdx.x;    // 128 features

    int lo = 0, hi = NN;
    while (lo < hi) { int m = (lo + hi) >> 1; if (batch[m] < g) lo = m + 1; else hi = m; }
    int st = lo;
    lo = 0; hi = NN;
    while (lo < hi) { int m = (lo + hi) >> 1; if (batch[m] < g + 1) lo = m + 1; else hi = m; }
    int en = lo;

    float acc = 0.f;
    for (int n = st; n < en; ++n) acc += g_h[(size_t)n * 128 + f];
    float cnt = (float)(en - st);
    g_pool[g * 128 + f] = acc / fmaxf(cnt, 1.0f);
}

// ---------------- final readout: out[g, 32] = kan(pool[g], W_read) ----------------
__global__ void read_kernel(float* __restrict__ out)
{
    __shared__ float phi[2048];
    __shared__ float part[32 * 8];
    int g   = blockIdx.x;
    int tid = threadIdx.x;

    if (tid < 128) {
        float x = g_pool[g * 128 + tid];
        float s1, c1;
        sincosf(x, &s1, &c1);
        float ck = c1, sk = s1;
#pragma unroll
        for (int hh = 0; hh < 8; ++hh) {
            phi[tid * 16 + hh]     = ck;
            phi[tid * 16 + 8 + hh] = sk;
            float cn = ck * c1 - sk * s1;
            sk = sk * c1 + ck * s1;
            ck = cn;
        }
    }
    __syncthreads();

    int o = tid >> 3, sg = tid & 7;
    float acc = 0.f;
    int k0 = sg * 256;
    for (int k = k0; k < k0 + 256; ++k)
        acc = fmaf(phi[k], g_wtr[k * 32 + o], acc);
    part[o * 8 + sg] = acc;
    __syncthreads();

    if (tid < 32) {
        float s = 0.f;
#pragma unroll
        for (int j = 0; j < 8; ++j) s += part[tid * 8 + j];
        out[g * 32 + tid] = s;
    }
}

// ---------------- launch ----------------
extern "C" void kernel_launch(void* const* d_in, const int* in_sizes, int n_in,
                              void* d_out, int out_size)
{
    const float* features = (const float*)d_in[0];
    const int*   ei       = (const int*)  d_in[1];
    const int*   batch    = (const int*)  d_in[2];
    const float* W_embed  = (const float*)d_in[3];
    const float* W_mp     = (const float*)d_in[4];
    const float* W_read   = (const float*)d_in[5];
    float* out = (float*)d_out;

    // 1. repack weights to K-major
    transpose_embed<<<(1024 * 128 + 255) / 256, 256>>>(W_embed);
    for (int l = 0; l < NL; ++l)
        transpose_mp<<<(2048 * 128 + 255) / 256, 256>>>(W_mp, l);
    transpose_read<<<(2048 * 32 + 255) / 256, 256>>>(W_read);

    // 2. degrees + dinv
    deg_init_kernel <<<(NN + 255) / 256, 256>>>();
    deg_count_kernel<<<(EE + 255) / 256, 256>>>(ei);
    dinv_kernel     <<<(NN + 255) / 256, 256>>>();

    // 3. CSR build (by destination col)
    scan_kernel<<<1, 1024>>>();
    fill_kernel<<<(EE + 255) / 256, 256>>>(ei);

    // 4. embed
    const int GK = (NN + 127) / 128;   // 391 tiles
    kan_embed_kernel<<<GK, 256>>>(features);

    // 5. message-passing layers: kan -> gather-aggregate
    for (int l = 0; l < NL; ++l) {
        kan_mp_kernel<<<GK, 256>>>(l);
        agg_kernel<<<(NN * 32 + 255) / 256, 256>>>();
    }

    // 6. pool + readout
    pool_kernel<<<NG, 128>>>(batch);
    read_kernel<<<NG, 256>>>(out);
}